// round 16
// baseline (speedup 1.0000x reference)
#include <cuda_runtime.h>
#include <math.h>
#include <stdint.h>

// Hyp-MLR: N=4096, C=256, D=128, CURV=1 — tf32 mma.sync, fragment-major smem.
// Per CTA: D[128,128] = X[128,128k] · W^T, W = [P_blk(64); A_blk(64)].
// 3-pass split: D = Xh·Wh + Xh·Wl + Xl·Wh (hi=tf32-rna fp32, lo=bf16).
// R15: tiles stored FRAGMENT-MAJOR ([tile][ks][lane][regs]) so the mainloop
// loads each mma fragment with one vector LDS (12 LDS/warp/kstep vs 32
// scalar) — attacks the LDS structural floor that capped R14. Stats are
// shuffle-reduced inside the fill (warp = one row per iteration).

#define N_TOT 4096
#define C_TOT 256
#define D_TOT 128
#define BM   128
#define BCLS 64
#define ABLK 132    // floats per (tm,ks) A-block (128 data + 4 pad)
#define BBLK 66     // floats per (tn,ks) B-block (64 data + 2 pad)
#define A_TILE_F (8 * 16 * ABLK)     // 16896 floats
#define B_TILE_F (16 * 16 * BBLK)    // 16896 floats
// byte offsets
#define OFF_XH 0
#define OFF_WH (A_TILE_F * 4)                  // 67584
#define OFF_XL (OFF_WH + B_TILE_F * 4)         // 135168 (bf16, same idx space)
#define OFF_WL (OFF_XL + A_TILE_F * 2)         // 168960 (bf16)
#define OFF_ST (OFF_WL + B_TILE_F * 2)         // 202752
#define SMEM_BYTES (OFF_ST + 384 * 4)          // 204288
#define DSTR 132
#define LN2F 0.69314718055994530942f

__device__ __forceinline__ float fast_rcp(float x) {
    float y; asm("rcp.approx.f32 %0, %1;" : "=f"(y) : "f"(x)); return y;
}
__device__ __forceinline__ float fast_sqrt(float x) {
    float y; asm("sqrt.approx.f32 %0, %1;" : "=f"(y) : "f"(x)); return y;
}
__device__ __forceinline__ float fast_lg2(float x) {
    float y; asm("lg2.approx.f32 %0, %1;" : "=f"(y) : "f"(x)); return y;
}
__device__ __forceinline__ float dot4(float4 a, float4 b) {
    return a.x * b.x + a.y * b.y + a.z * b.z + a.w * b.w;
}
__device__ __forceinline__ uint32_t cvt_tf32(float x) {
    uint32_t r; asm("cvt.rna.tf32.f32 %0, %1;" : "=r"(r) : "f"(x)); return r;
}
__device__ __forceinline__ uint16_t f2bf(float x) {
    uint16_t r; asm("cvt.rn.bf16.f32 %0, %1;" : "=h"(r) : "f"(x)); return r;
}
__device__ __forceinline__ float wred(float s) {
    #pragma unroll
    for (int o = 16; o > 0; o >>= 1) s += __shfl_xor_sync(~0u, s, o);
    return s;
}
// m16n8k8 tf32 mma: A row-major, B col-major, fp32 accumulate.
__device__ __forceinline__ void mma8(float* c, const uint32_t* a, const uint32_t* b) {
    asm volatile(
        "mma.sync.aligned.m16n8k8.row.col.f32.tf32.tf32.f32 "
        "{%0,%1,%2,%3}, {%4,%5,%6,%7}, {%8,%9}, {%0,%1,%2,%3};"
        : "+f"(c[0]), "+f"(c[1]), "+f"(c[2]), "+f"(c[3])
        : "r"(a[0]), "r"(a[1]), "r"(a[2]), "r"(a[3]), "r"(b[0]), "r"(b[1]));
}

__global__ __launch_bounds__(512, 1) void hyp_mlr_mma_kernel(
    const float* __restrict__ X,   // (N, D)
    const float* __restrict__ A,   // (C, D)
    const float* __restrict__ P,   // (C, D)
    float* __restrict__ out)       // (N, C)
{
    extern __shared__ char smem[];
    float*    XhF = (float*)(smem + OFF_XH);     // frag-major tf32-hi of X
    float*    WhF = (float*)(smem + OFF_WH);     // frag-major tf32-hi of W
    uint16_t* XlF = (uint16_t*)(smem + OFF_XL);  // frag-major bf16-lo of X
    uint16_t* WlF = (uint16_t*)(smem + OFF_WL);  // frag-major bf16-lo of W
    float* sx2  = (float*)(smem + OFF_ST);       // [128]
    float* sp2  = sx2 + 128;                     // [64]
    float* spa  = sp2 + 64;
    float* sina = spa + 64;
    float* sw2  = sina + 64;

    const int tid = threadIdx.x;
    const int wid = tid >> 5;     // 0..15
    const int lid = tid & 31;
    const int c0  = blockIdx.x * BCLS;
    const int n0  = blockIdx.y * BM;

    // ---- Fill X (frag-major) + per-row x2 via warp reduce (warp = 1 row/iter)
    #pragma unroll
    for (int i = 0; i < 8; i++) {
        const int row = i * 16 + wid;        // id>>5 with id = i*512+tid
        const int cc  = lid;                 // float4 chunk 0..31
        float4 v = *(const float4*)&X[(size_t)(n0 + row) * D_TOT + cc * 4];
        const int tm = row >> 4, rr = row & 15, gg = rr & 7, half = rr >> 3;
        const int ks = cc >> 1,  rh = cc & 1;
        const int base = (tm * 16 + ks) * ABLK + half + rh * 2;  // + (gg*4+j)*4
        float vv[4] = {v.x, v.y, v.z, v.w};
        #pragma unroll
        for (int j = 0; j < 4; j++) {
            const int idx = base + (gg * 4 + j) * 4;
            float h = __uint_as_float(cvt_tf32(vv[j]));
            XhF[idx] = h;
            XlF[idx] = f2bf(vv[j] - h);
        }
        float s = wred(dot4(v, v));
        if (lid == 0) sx2[row] = s;
    }
    // ---- Fill W (rows 0-63 = P, 64-127 = A) + class stats (p2, a2, pa).
    float4 pv_save[4];
    #pragma unroll
    for (int i = 0; i < 8; i++) {
        const int row = i * 16 + wid;
        const int cc  = lid;
        const float* src = (row < 64)
            ? &P[(size_t)(c0 + row) * D_TOT]
            : &A[(size_t)(c0 + row - 64) * D_TOT];
        float4 v = *(const float4*)&src[cc * 4];
        const int tn = row >> 3, gg = row & 7;
        const int ks = cc >> 1,  rh = cc & 1;
        const int base = (tn * 16 + ks) * BBLK + rh;             // + (gg*4+j)*2
        float vv[4] = {v.x, v.y, v.z, v.w};
        #pragma unroll
        for (int j = 0; j < 4; j++) {
            const int idx = base + (gg * 4 + j) * 2;
            float h = __uint_as_float(cvt_tf32(vv[j]));
            WhF[idx] = h;
            WlF[idx] = f2bf(vv[j] - h);
        }
        if (i < 4) {
            pv_save[i] = v;
            float s = wred(dot4(v, v));
            if (lid == 0) sp2[row] = s;
        } else {
            float4 p = pv_save[i - 4];
            float s2 = wred(dot4(v, v));      // a2
            float s3 = wred(dot4(v, p));      // p.a
            if (lid == 0) {
                const int r = row - 64;
                spa[r] = s3;
                float na = sqrtf(s2);
                sina[r] = fast_rcp(fmaxf(na, 1e-12f));
                sw2[r]  = 2.0f * na * LN2F;
            }
        }
    }
    __syncthreads();

    // ---- Mainloop: warp grid 4m x 4n; vector LDS -> mma (12 LDS / kstep).
    const int band = wid & 3;       // row band: tm = band*2 + mt
    const int quad = wid >> 2;      // col quarter: tn = quad*4 + nt

    float acc[2][4][4];
    #pragma unroll
    for (int mt = 0; mt < 2; mt++)
        #pragma unroll
        for (int nt = 0; nt < 4; nt++)
            #pragma unroll
            for (int e = 0; e < 4; e++) acc[mt][nt][e] = 0.f;

    #pragma unroll 4
    for (int ks = 0; ks < 16; ks++) {
        uint32_t ah[2][4], al[2][4];
        #pragma unroll
        for (int mt = 0; mt < 2; mt++) {
            const int ab = ((band * 2 + mt) * 16 + ks) * ABLK + lid * 4;
            float4 h = *(const float4*)&XhF[ab];       // LDS.128: a0..a3
            ah[mt][0] = __float_as_uint(h.x);
            ah[mt][1] = __float_as_uint(h.y);
            ah[mt][2] = __float_as_uint(h.z);
            ah[mt][3] = __float_as_uint(h.w);
            uint2 u = *(const uint2*)&XlF[ab];         // LDS.64: 4 bf16
            al[mt][0] = u.x << 16;
            al[mt][1] = u.x & 0xFFFF0000u;
            al[mt][2] = u.y << 16;
            al[mt][3] = u.y & 0xFFFF0000u;
        }
        uint32_t bh[4][2], bl[4][2];
        #pragma unroll
        for (int nt = 0; nt < 4; nt++) {
            const int bb = ((quad * 4 + nt) * 16 + ks) * BBLK + lid * 2;
            float2 h = *(const float2*)&WhF[bb];       // LDS.64: b0,b1
            bh[nt][0] = __float_as_uint(h.x);
            bh[nt][1] = __float_as_uint(h.y);
            uint32_t u = *(const uint32_t*)&WlF[bb];   // LDS.32: 2 bf16
            bl[nt][0] = u << 16;
            bl[nt][1] = u & 0xFFFF0000u;
        }
        // 3 passes: hi*hi, hi*lo, lo*hi.
        #pragma unroll
        for (int mt = 0; mt < 2; mt++)
            #pragma unroll
            for (int nt = 0; nt < 4; nt++)
                mma8(acc[mt][nt], ah[mt], bh[nt]);
        #pragma unroll
        for (int mt = 0; mt < 2; mt++)
            #pragma unroll
            for (int nt = 0; nt < 4; nt++)
                mma8(acc[mt][nt], ah[mt], bl[nt]);
        #pragma unroll
        for (int mt = 0; mt < 2; mt++)
            #pragma unroll
            for (int nt = 0; nt < 4; nt++)
                mma8(acc[mt][nt], al[mt], bh[nt]);
    }

    // ---- Stage D into smem (reuse XhF: exactly 128*132 floats).
    __syncthreads();
    float* Ds = XhF;
    {
        const int g   = lid >> 2;
        const int tig = lid & 3;
        const int mrow  = band * 32;
        const int wbase = quad * 32;
        #pragma unroll
        for (int mt = 0; mt < 2; mt++)
            #pragma unroll
            for (int nt = 0; nt < 4; nt++) {
                const int r   = mrow + mt * 16 + g;
                const int col = wbase + nt * 8 + tig * 2;
                float2 lo = {acc[mt][nt][0], acc[mt][nt][1]};
                float2 hi = {acc[mt][nt][2], acc[mt][nt][3]};
                *(float2*)&Ds[r * DSTR + col]       = lo;
                *(float2*)&Ds[(r + 8) * DSTR + col] = hi;
            }
    }
    __syncthreads();

    // ---- Epilogue: thread -> (row = tid>>2, 16-class quarter), fused math.
    {
        const int r  = tid >> 2;
        const int ch = (tid & 3) * 16;
        const float x2   = sx2[r];
        const float x2p1 = 1.0f + x2;
        const size_t obase = (size_t)(n0 + r) * C_TOT + c0 + ch;

        #pragma unroll
        for (int q = 0; q < 4; q++) {
            float4 xp4 = *(const float4*)&Ds[r * DSTR + ch + q * 4];
            float4 xa4 = *(const float4*)&Ds[r * DSTR + 64 + ch + q * 4];
            float xpv[4] = {xp4.x, xp4.y, xp4.z, xp4.w};
            float xav[4] = {xa4.x, xa4.y, xa4.z, xa4.w};
            float res[4];
            #pragma unroll
            for (int e = 0; e < 4; e++) {
                const int c = ch + q * 4 + e;
                float p2  = sp2[c];
                float bet = 1.0f - p2;
                float txy = -2.0f * xpv[e];              // 2*xy
                float alpha = x2p1 + txy;                // 1 + 2xy + x2
                float den   = fmaf(p2, x2, 1.0f + txy);
                float s   = fmaf(alpha, fmaf(alpha, p2, bet * txy),
                                 bet * bet * x2);
                float num = fmaf(bet, xav[e], -alpha * spa[c]);
                float d2ms = fmaf(den, den, -s);         // den^2 - s
                float arg = 2.0f * den * num * sina[c] * fast_rcp(d2ms);
                float qq  = arg + fast_sqrt(fmaf(arg, arg, 1.0f));
                res[e] = sw2[c] * fast_lg2(qq);          // 2*na*ln2*log2
            }
            float4 o = {res[0], res[1], res[2], res[3]};
            *(float4*)&out[obase + q * 4] = o;
        }
    }
}

extern "C" void kernel_launch(void* const* d_in, const int* in_sizes, int n_in,
                              void* d_out, int out_size) {
    const float* X = (const float*)d_in[0];   // output_before (N, D)
    const float* A = (const float*)d_in[1];   // a_mlr (C, D)
    const float* P = (const float*)d_in[2];   // p_mlr (C, D)
    float* out = (float*)d_out;               // (N, C)

    cudaFuncSetAttribute(hyp_mlr_mma_kernel,
                         cudaFuncAttributeMaxDynamicSharedMemorySize,
                         SMEM_BYTES);

    dim3 grid(C_TOT / BCLS, N_TOT / BM);      // (4, 32) = 128 CTAs, one wave
    hyp_mlr_mma_kernel<<<grid, 512, SMEM_BYTES>>>(X, A, P, out);
}

// round 17
// speedup vs baseline: 1.9321x; 1.9321x over previous
#include <cuda_runtime.h>
#include <math.h>
#include <stdint.h>

// Hyp-MLR: N=4096, C=256, D=128, CURV=1 — bf16x2-split mma.sync (sm_80 PTX).
// Per CTA: D[128,128] = X[128,128k] · W^T, W = [P_blk(64); A_blk(64)].
// 3-pass split: D = Xh·Wh + Xh·Wl + Xl·Wh, hi/lo both bf16 (~2^-16 dot err,
// 60x under threshold). m16n8k16 bf16 mma: half the mma count of tf32-k8 at
// ~2x rate, fragments load as natural packed bf16x2 words (LDS.32 each).
// Structure (fill / stats / staging / epilogue) is R14 verbatim.

#define N_TOT 4096
#define C_TOT 256
#define D_TOT 128
#define BM   128
#define BCLS 64
#define STRH 136              // bf16 per row (128 data + 8 pad); 68 words ≡ 4 mod 32
#define HW   68               // 32-bit words per row
#define TILEB (128 * STRH * 2)                // 34816 B per bf16 tile
#define OFF_XH 0
#define OFF_XL (1 * TILEB)                    // 34816
#define OFF_WH (2 * TILEB)                    // 69632
#define OFF_WL (3 * TILEB)                    // 104448
#define OFF_ST (4 * TILEB)                    // 139264
#define SMEM_BYTES (OFF_ST + 384 * 4)         // 140800
#define DSTR 132              // D staging stride (floats), reuses Xh+Xl region
#define LN2F 0.69314718055994530942f

__device__ __forceinline__ float fast_rcp(float x) {
    float y; asm("rcp.approx.f32 %0, %1;" : "=f"(y) : "f"(x)); return y;
}
__device__ __forceinline__ float fast_sqrt(float x) {
    float y; asm("sqrt.approx.f32 %0, %1;" : "=f"(y) : "f"(x)); return y;
}
__device__ __forceinline__ float fast_lg2(float x) {
    float y; asm("lg2.approx.f32 %0, %1;" : "=f"(y) : "f"(x)); return y;
}
// pack two f32 -> bf16x2 word: low half = lo (even k), high half = hi (odd k)
__device__ __forceinline__ uint32_t pack_bf(float lo, float hi) {
    uint32_t r; asm("cvt.rn.bf16x2.f32 %0, %1, %2;" : "=r"(r) : "f"(hi), "f"(lo));
    return r;
}
// m16n8k16 bf16 mma: A row-major, B col-major, fp32 accumulate.
__device__ __forceinline__ void mmabf(float* c, const uint32_t* a, const uint32_t* b) {
    asm volatile(
        "mma.sync.aligned.m16n8k16.row.col.f32.bf16.bf16.f32 "
        "{%0,%1,%2,%3}, {%4,%5,%6,%7}, {%8,%9}, {%0,%1,%2,%3};"
        : "+f"(c[0]), "+f"(c[1]), "+f"(c[2]), "+f"(c[3])
        : "r"(a[0]), "r"(a[1]), "r"(a[2]), "r"(a[3]), "r"(b[0]), "r"(b[1]));
}
// reconstruct the two f32 elements of a (hi_word, lo_word) bf16x2 pair
__device__ __forceinline__ float2 rec2(uint32_t h, uint32_t l) {
    float e0 = __uint_as_float(h << 16) + __uint_as_float(l << 16);
    float e1 = __uint_as_float(h & 0xFFFF0000u) + __uint_as_float(l & 0xFFFF0000u);
    return {e0, e1};
}

__global__ __launch_bounds__(512, 1) void hyp_mlr_mma_kernel(
    const float* __restrict__ X,   // (N, D)
    const float* __restrict__ A,   // (C, D)
    const float* __restrict__ P,   // (C, D)
    float* __restrict__ out)       // (N, C)
{
    extern __shared__ char smem[];
    uint32_t* Xh = (uint32_t*)(smem + OFF_XH);   // [128][HW] bf16x2 hi of X
    uint32_t* Xl = (uint32_t*)(smem + OFF_XL);   // lo of X
    uint32_t* Wh = (uint32_t*)(smem + OFF_WH);   // hi of W = [P;A]
    uint32_t* Wl = (uint32_t*)(smem + OFF_WL);   // lo of W
    float* sx2  = (float*)(smem + OFF_ST);       // [128]
    float* sp2  = sx2 + 128;                     // [64]
    float* spa  = sp2 + 64;
    float* sina = spa + 64;
    float* sw2  = sina + 64;

    const int tid = threadIdx.x;
    const int wid = tid >> 5;     // 0..15
    const int lid = tid & 31;
    const int g   = lid >> 2;     // group (0..7)
    const int tig = lid & 3;      // thread in group
    const int c0  = blockIdx.x * BCLS;
    const int n0  = blockIdx.y * BM;

    // ---- Fill X: hi/lo bf16 split (word = packed k-pair). Vector STS (uint2).
    #pragma unroll
    for (int i = 0; i < 8; i++) {
        int id  = i * 512 + tid;
        int row = id >> 5;
        int cc  = id & 31;                 // float4 chunk = 2 words
        float4 v = *(const float4*)&X[(size_t)(n0 + row) * D_TOT + cc * 4];
        uint32_t h0 = pack_bf(v.x, v.y);
        uint32_t h1 = pack_bf(v.z, v.w);
        float l0 = v.x - __uint_as_float(h0 << 16);
        float l1 = v.y - __uint_as_float(h0 & 0xFFFF0000u);
        float l2 = v.z - __uint_as_float(h1 << 16);
        float l3 = v.w - __uint_as_float(h1 & 0xFFFF0000u);
        uint2 hq = {h0, h1};
        uint2 lq = {pack_bf(l0, l1), pack_bf(l2, l3)};
        *(uint2*)&Xh[row * HW + cc * 2] = hq;
        *(uint2*)&Xl[row * HW + cc * 2] = lq;
    }
    // ---- Fill W: rows 0-63 = P, 64-127 = A.
    #pragma unroll
    for (int i = 0; i < 8; i++) {
        int id  = i * 512 + tid;
        int row = id >> 5;
        int cc  = id & 31;
        const float* src = (row < 64)
            ? &P[(size_t)(c0 + row) * D_TOT]
            : &A[(size_t)(c0 + row - 64) * D_TOT];
        float4 v = *(const float4*)&src[cc * 4];
        uint32_t h0 = pack_bf(v.x, v.y);
        uint32_t h1 = pack_bf(v.z, v.w);
        float l0 = v.x - __uint_as_float(h0 << 16);
        float l1 = v.y - __uint_as_float(h0 & 0xFFFF0000u);
        float l2 = v.z - __uint_as_float(h1 << 16);
        float l3 = v.w - __uint_as_float(h1 & 0xFFFF0000u);
        uint2 hq = {h0, h1};
        uint2 lq = {pack_bf(l0, l1), pack_bf(l2, l3)};
        *(uint2*)&Wh[row * HW + cc * 2] = hq;
        *(uint2*)&Wl[row * HW + cc * 2] = lq;
    }
    __syncthreads();

    // ---- Stats from hi+lo tiles (reconstruction err ~2^-17, immaterial).
    if (tid < 128) {
        float s = 0.f;
        #pragma unroll
        for (int w = 0; w < 64; w += 2) {
            uint2 h = *(const uint2*)&Xh[tid * HW + w];
            uint2 l = *(const uint2*)&Xl[tid * HW + w];
            float2 e0 = rec2(h.x, l.x);
            float2 e1 = rec2(h.y, l.y);
            s += e0.x * e0.x + e0.y * e0.y + e1.x * e1.x + e1.y * e1.y;
        }
        sx2[tid] = s;
    } else if (tid < 192) {
        int r = tid - 128;
        float p2 = 0.f, a2 = 0.f, pa = 0.f;
        #pragma unroll
        for (int w = 0; w < 64; w += 2) {
            uint2 ph = *(const uint2*)&Wh[r * HW + w];
            uint2 pl = *(const uint2*)&Wl[r * HW + w];
            uint2 ah = *(const uint2*)&Wh[(r + 64) * HW + w];
            uint2 al = *(const uint2*)&Wl[(r + 64) * HW + w];
            float2 p0 = rec2(ph.x, pl.x), p1 = rec2(ph.y, pl.y);
            float2 a0 = rec2(ah.x, al.x), a1 = rec2(ah.y, al.y);
            p2 += p0.x * p0.x + p0.y * p0.y + p1.x * p1.x + p1.y * p1.y;
            a2 += a0.x * a0.x + a0.y * a0.y + a1.x * a1.x + a1.y * a1.y;
            pa += p0.x * a0.x + p0.y * a0.y + p1.x * a1.x + p1.y * a1.y;
        }
        sp2[r] = p2;
        spa[r] = pa;
        float na = sqrtf(a2);
        sina[r] = fast_rcp(fmaxf(na, 1e-12f));
        sw2[r]  = 2.0f * na * LN2F;
    }
    // stats ordered vs epilogue readers by the post-mainloop __syncthreads

    // ---- Mainloop: warp grid 4m x 4n; 8 ksteps of K=16; pure LDS.32 -> mma.
    const int mrow  = (wid & 3) * 32;
    const int wbase = (wid >> 2) * 32;

    float acc[2][4][4];
    #pragma unroll
    for (int mt = 0; mt < 2; mt++)
        #pragma unroll
        for (int nt = 0; nt < 4; nt++)
            #pragma unroll
            for (int e = 0; e < 4; e++) acc[mt][nt][e] = 0.f;

    #pragma unroll 4
    for (int ks = 0; ks < 8; ks++) {
        const int ko = ks * 8 + tig;       // word offset within row
        uint32_t ah[2][4], al[2][4];
        #pragma unroll
        for (int mt = 0; mt < 2; mt++) {
            const int o = (mrow + mt * 16 + g) * HW + ko;
            ah[mt][0] = Xh[o];
            ah[mt][1] = Xh[o + 8 * HW];
            ah[mt][2] = Xh[o + 4];
            ah[mt][3] = Xh[o + 8 * HW + 4];
            al[mt][0] = Xl[o];
            al[mt][1] = Xl[o + 8 * HW];
            al[mt][2] = Xl[o + 4];
            al[mt][3] = Xl[o + 8 * HW + 4];
        }
        uint32_t bh[4][2], bl[4][2];
        #pragma unroll
        for (int nt = 0; nt < 4; nt++) {
            const int o = (wbase + nt * 8 + g) * HW + ko;
            bh[nt][0] = Wh[o];
            bh[nt][1] = Wh[o + 4];
            bl[nt][0] = Wl[o];
            bl[nt][1] = Wl[o + 4];
        }
        // 3 passes: hi*hi, hi*lo, lo*hi.
        #pragma unroll
        for (int mt = 0; mt < 2; mt++)
            #pragma unroll
            for (int nt = 0; nt < 4; nt++)
                mmabf(acc[mt][nt], ah[mt], bh[nt]);
        #pragma unroll
        for (int mt = 0; mt < 2; mt++)
            #pragma unroll
            for (int nt = 0; nt < 4; nt++)
                mmabf(acc[mt][nt], ah[mt], bl[nt]);
        #pragma unroll
        for (int mt = 0; mt < 2; mt++)
            #pragma unroll
            for (int nt = 0; nt < 4; nt++)
                mmabf(acc[mt][nt], al[mt], bh[nt]);
    }

    // ---- Stage D into smem (reuse Xh+Xl region: 128*DSTR*4 = 67584 B fits).
    __syncthreads();
    float* Ds = (float*)smem;
    #pragma unroll
    for (int mt = 0; mt < 2; mt++)
        #pragma unroll
        for (int nt = 0; nt < 4; nt++) {
            const int r   = mrow + mt * 16 + g;
            const int col = wbase + nt * 8 + tig * 2;
            float2 lo = {acc[mt][nt][0], acc[mt][nt][1]};
            float2 hi = {acc[mt][nt][2], acc[mt][nt][3]};
            *(float2*)&Ds[r * DSTR + col]       = lo;
            *(float2*)&Ds[(r + 8) * DSTR + col] = hi;
        }
    __syncthreads();

    // ---- Epilogue: thread -> (row = tid>>2, 16-class quarter), fused math.
    {
        const int r  = tid >> 2;
        const int ch = (tid & 3) * 16;
        const float x2   = sx2[r];
        const float x2p1 = 1.0f + x2;
        const size_t obase = (size_t)(n0 + r) * C_TOT + c0 + ch;

        #pragma unroll
        for (int q = 0; q < 4; q++) {
            float4 xp4 = *(const float4*)&Ds[r * DSTR + ch + q * 4];
            float4 xa4 = *(const float4*)&Ds[r * DSTR + 64 + ch + q * 4];
            float xpv[4] = {xp4.x, xp4.y, xp4.z, xp4.w};
            float xav[4] = {xa4.x, xa4.y, xa4.z, xa4.w};
            float res[4];
            #pragma unroll
            for (int e = 0; e < 4; e++) {
                const int c = ch + q * 4 + e;
                float p2  = sp2[c];
                float bet = 1.0f - p2;
                float txy = -2.0f * xpv[e];              // 2*xy
                float alpha = x2p1 + txy;                // 1 + 2xy + x2
                float den   = fmaf(p2, x2, 1.0f + txy);
                float s   = fmaf(alpha, fmaf(alpha, p2, bet * txy),
                                 bet * bet * x2);
                float num = fmaf(bet, xav[e], -alpha * spa[c]);
                float d2ms = fmaf(den, den, -s);         // den^2 - s
                float arg = 2.0f * den * num * sina[c] * fast_rcp(d2ms);
                float qq  = arg + fast_sqrt(fmaf(arg, arg, 1.0f));
                res[e] = sw2[c] * fast_lg2(qq);          // 2*na*ln2*log2
            }
            float4 o = {res[0], res[1], res[2], res[3]};
            *(float4*)&out[obase + q * 4] = o;
        }
    }
}

extern "C" void kernel_launch(void* const* d_in, const int* in_sizes, int n_in,
                              void* d_out, int out_size) {
    const float* X = (const float*)d_in[0];   // output_before (N, D)
    const float* A = (const float*)d_in[1];   // a_mlr (C, D)
    const float* P = (const float*)d_in[2];   // p_mlr (C, D)
    float* out = (float*)d_out;               // (N, C)

    cudaFuncSetAttribute(hyp_mlr_mma_kernel,
                         cudaFuncAttributeMaxDynamicSharedMemorySize,
                         SMEM_BYTES);

    dim3 grid(C_TOT / BCLS, N_TOT / BM);      // (4, 32) = 128 CTAs, one wave
    hyp_mlr_mma_kernel<<<grid, 512, SMEM_BYTES>>>(X, A, P, out);
}